// round 16
// baseline (speedup 1.0000x reference)
#include <cuda_runtime.h>
#include <cstdint>

#define C_DIM 270
#define T_DIM 2000
#define O_DIM 270
#define D_DIM 2048

// ---------------- scratch (static device globals; no allocation) ----------------
__device__ float g_E[C_DIM * D_DIM];           // fourier embedding [C, D]
__device__ float g_Spart[16 * O_DIM * C_DIM];  // split-K score partials
__device__ uint4 g_Wf[18 * 34 * 32];           // softmaxed W in tf32 MMA A-fragment layout

__device__ __forceinline__ unsigned f2tf(float f) {
    unsigned r;
    asm("cvt.rna.tf32.f32 %0, %1;" : "=r"(r) : "f"(f));
    return r;
}
__device__ __forceinline__ uint32_t smem_u32(const void* p) {
    uint32_t a;
    asm("{ .reg .u64 t; cvta.to.shared.u64 t, %1; cvt.u32.u64 %0, t; }" : "=r"(a) : "l"(p));
    return a;
}
__device__ __forceinline__ void cp_async16(uint32_t dst, const void* src, int sz) {
    asm volatile("cp.async.cg.shared.global [%0], [%1], 16, %2;"
                 :: "r"(dst), "l"(src), "r"(sz));
}
#define CP_COMMIT() asm volatile("cp.async.commit_group;" ::: "memory")
#define CP_WAIT1() asm volatile("cp.async.wait_group 1;" ::: "memory")
#define CP_WAIT0() asm volatile("cp.async.wait_group 0;" ::: "memory")

// ---------------- kernel 1: fourier embedding via angle-sum factorization ----------------
__global__ void cm_embed_kernel(const float* __restrict__ layout) {
    int c = blockIdx.x;
    int tid = threadIdx.x;  // 256
    const float KK = 4.48798950512827605f;  // 2*pi / (1 + 2*0.2)
    __shared__ float cA[32], sA[32], cB[32], sB[32];

    if (tid < 32) {
        float px = layout[2 * c + 0] + 0.2f;
        sincosf(px * KK * (float)tid, &sA[tid], &cA[tid]);
    } else if (tid < 64) {
        int j = tid - 32;
        float py = layout[2 * c + 1] + 0.2f;
        sincosf(py * KK * (float)j, &sB[j], &cB[j]);
    }
    __syncthreads();

    for (int idx = tid; idx < 1024; idx += 256) {
        int i = idx >> 5, j = idx & 31;
        float ca = cA[i], sa = sA[i], cb = cB[j], sb = sB[j];
        g_E[c * D_DIM + idx] = ca * cb - sa * sb;          // cos(a+b)
        g_E[c * D_DIM + 1024 + idx] = sa * cb + ca * sb;   // sin(a+b)
    }
}

// ---------------- kernel 2: scores S[o,c] = sum_d H[o,d]*E[c,d] ----------------
// 96x96 tile, 6x6 acc, 256 threads, split-K=16 (128 d per slice). Grid (3,3,16).
__global__ void cm_scores_kernel(const float* __restrict__ heads) {
    __shared__ float As[96][17];   // [o][k]
    __shared__ float Bs[96][17];   // [c][k]
    int o0 = blockIdx.x * 96;
    int c0 = blockIdx.y * 96;
    int kz = blockIdx.z;
    int d_base = kz * 128;
    int tid = threadIdx.x;          // 256
    int tx = tid & 15, ty = tid >> 4;
    float acc[6][6] = {};

    for (int dt = 0; dt < 128; dt += 16) {
#pragma unroll
        for (int i = 0; i < 2; ++i) {
            int idx = tid + i * 256;
            if (idx < 384) {
                int row = idx >> 2, col = (idx & 3) * 4;
                int d = d_base + dt + col;
                {
                    int go = o0 + row;
                    float4 v = (go < O_DIM) ? *(const float4*)&heads[(size_t)go * D_DIM + d]
                                            : make_float4(0.f, 0.f, 0.f, 0.f);
                    As[row][col] = v.x; As[row][col + 1] = v.y;
                    As[row][col + 2] = v.z; As[row][col + 3] = v.w;
                }
                {
                    int gc = c0 + row;
                    float4 v = (gc < C_DIM) ? *(const float4*)&g_E[(size_t)gc * D_DIM + d]
                                            : make_float4(0.f, 0.f, 0.f, 0.f);
                    Bs[row][col] = v.x; Bs[row][col + 1] = v.y;
                    Bs[row][col + 2] = v.z; Bs[row][col + 3] = v.w;
                }
            }
        }
        __syncthreads();
#pragma unroll
        for (int k = 0; k < 16; ++k) {
            float a[6], b[6];
#pragma unroll
            for (int i = 0; i < 6; ++i) a[i] = As[ty * 6 + i][k];
#pragma unroll
            for (int j = 0; j < 6; ++j) b[j] = Bs[tx * 6 + j][k];
#pragma unroll
            for (int i = 0; i < 6; ++i)
#pragma unroll
                for (int j = 0; j < 6; ++j) acc[i][j] += a[i] * b[j];
        }
        __syncthreads();
    }
#pragma unroll
    for (int i = 0; i < 6; ++i) {
        int o = o0 + ty * 6 + i;
        if (o >= O_DIM) continue;
#pragma unroll
        for (int j = 0; j < 6; ++j) {
            int c = c0 + tx * 6 + j;
            if (c < C_DIM) g_Spart[kz * (O_DIM * C_DIM) + o * C_DIM + c] = acc[i][j];
        }
    }
}

// ---------------- kernel 3: softmax over c, scattered straight into fragment layout ----------------
__global__ void cm_softmax_kernel(const float* __restrict__ layout) {
    int o = blockIdx.x;         // 0..287
    int tid = threadIdx.x;      // 288 threads
    int c = tid;
    int mblk = o >> 4, rr = o & 15;
    uint32_t* wf = (uint32_t*)g_Wf;

    auto scatter = [&](float v) {
        if (c >= 272) return;
        int kblk = c >> 3, q = c & 7;
        int lane, comp;
        if (q < 4) { lane = ((rr & 7) << 2) | q;       comp = (rr < 8) ? 0 : 1; }
        else       { lane = ((rr & 7) << 2) | (q - 4); comp = (rr < 8) ? 2 : 3; }
        wf[(((mblk * 34 + kblk) * 32 + lane) << 2) | comp] = f2tf(v);
    };

    if (o >= O_DIM) { scatter(0.f); return; }

    const float NEGINF = -__int_as_float(0x7f800000);
    float val = NEGINF;
    if (c < C_DIM) {
        float s = 0.f;
#pragma unroll
        for (int kz = 0; kz < 16; ++kz) s += g_Spart[kz * (O_DIM * C_DIM) + o * C_DIM + c];
        bool invalid = (layout[2 * c] == -0.1f) && (layout[2 * c + 1] == -0.1f);
        val = invalid ? NEGINF : s;
    }
    __shared__ float redm[9], reds[9];
    float m = val;
#pragma unroll
    for (int off = 16; off; off >>= 1) m = fmaxf(m, __shfl_xor_sync(0xffffffffu, m, off));
    if ((tid & 31) == 0) redm[tid >> 5] = m;
    __syncthreads();
    float mall = redm[0];
#pragma unroll
    for (int w = 1; w < 9; ++w) mall = fmaxf(mall, redm[w]);

    float e = (c < C_DIM) ? expf(val - mall) : 0.f;
    float s = e;
#pragma unroll
    for (int off = 16; off; off >>= 1) s += __shfl_xor_sync(0xffffffffu, s, off);
    if ((tid & 31) == 0) reds[tid >> 5] = s;
    __syncthreads();
    float tot = 0.f;
#pragma unroll
    for (int w = 0; w < 9; ++w) tot += reds[w];

    scatter(e / tot);   // c>=270 lanes have e==0 -> zero pad
}

// ---------------- kernel 4: out[b] = W @ x[b]  (tf32 mma.sync, 2-stage cp.async — R7 config) ----------------
#define BM 96
#define BN 128
#define BPADF 136   // 136 % 32 == 8 -> conflict-free tig groups; 16B aligned
#define KITERS 17   // 17 * k16 = 272

__global__ __launch_bounds__(128, 3) void cm_merge_kernel(const float* __restrict__ x,
                                                          float* __restrict__ out) {
    __shared__ float Bs[2][16 * BPADF];

    int mt = blockIdx.x % 3;   // m-tile fastest -> 3 CTAs share the x tile in L2
    int nt = blockIdx.x / 3;
    int b = blockIdx.y;
    int m0 = mt * BM;
    int t0 = nt * BN;
    const float* xb = x + (size_t)b * (C_DIM * T_DIM);
    float* ob = out + (size_t)b * (O_DIM * T_DIM);

    int tid = threadIdx.x;
    int lane = tid & 31, warp = tid >> 5;
    int wm = (warp & 1) * 48;          // 2 m-warps
    int wn = (warp >> 1) * 64;         // 2 n-warps of 64
    int gid = lane >> 2, tig = lane & 3;
    int mblkBase = mt * 6 + (warp & 1) * 3;

    uint32_t bs_base = smem_u32(&Bs[0][0]);

    float acc[3][8][4] = {};
    uint4 afA[3], afB[3];
    const uint4* wf = g_Wf;

    auto stage = [&](int it) {
        int buf = it & 1;
        int kg0 = it * 16;
        uint32_t base = bs_base + (uint32_t)buf * (16 * BPADF * 4);
#pragma unroll
        for (int i = 0; i < 4; ++i) {
            int idx = tid + i * 128;
            int row = idx >> 5, seg = idx & 31;
            int kg = kg0 + row;
            int t = t0 + seg * 4;
            int ok = (kg < C_DIM && t + 4 <= T_DIM);
            const float* src = &xb[(size_t)(ok ? kg : 0) * T_DIM + (ok ? t : 0)];
            cp_async16(base + (uint32_t)(row * BPADF + seg * 4) * 4, src, ok ? 16 : 0);
        }
        CP_COMMIT();
    };
    auto loadA = [&](uint4* af, int kblk) {
        kblk = kblk < 33 ? kblk : 33;
#pragma unroll
        for (int mi = 0; mi < 3; ++mi)
            af[mi] = wf[((mblkBase + mi) * 34 + kblk) * 32 + lane];
    };
    auto compute = [&](int buf, int kk, const uint4* af) {
        unsigned bf[8][2];
#pragma unroll
        for (int ni = 0; ni < 8; ++ni) {
            int cN = wn + ni * 8 + gid;
            bf[ni][0] = __float_as_uint(Bs[buf][(kk + tig) * BPADF + cN]);
            bf[ni][1] = __float_as_uint(Bs[buf][(kk + tig + 4) * BPADF + cN]);
        }
#pragma unroll
        for (int mi = 0; mi < 3; ++mi)
#pragma unroll
            for (int ni = 0; ni < 8; ++ni) {
                asm volatile(
                    "mma.sync.aligned.m16n8k8.row.col.f32.tf32.tf32.f32 "
                    "{%0,%1,%2,%3},{%4,%5,%6,%7},{%8,%9},{%0,%1,%2,%3};"
                    : "+f"(acc[mi][ni][0]), "+f"(acc[mi][ni][1]),
                      "+f"(acc[mi][ni][2]), "+f"(acc[mi][ni][3])
                    : "r"(af[mi].x), "r"(af[mi].y), "r"(af[mi].z), "r"(af[mi].w),
                      "r"(bf[ni][0]), "r"(bf[ni][1]));
            }
    };

    stage(0);
    stage(1);
    loadA(afA, 0);
#pragma unroll 1
    for (int it = 0; it < KITERS; ++it) {
        if (it + 1 < KITERS) { CP_WAIT1(); } else { CP_WAIT0(); }
        __syncthreads();
        loadA(afB, 2 * it + 1);
        compute(it & 1, 0, afA);
        loadA(afA, 2 * it + 2);
        compute(it & 1, 8, afB);
        __syncthreads();
        if (it + 2 < KITERS) stage(it + 2);
    }

    // epilogue
#pragma unroll
    for (int mi = 0; mi < 3; ++mi) {
        int o = m0 + wm + mi * 16 + gid;
#pragma unroll
        for (int ni = 0; ni < 8; ++ni) {
            int t = t0 + wn + ni * 8 + tig * 2;
            if (t < T_DIM) {
                if (o < O_DIM) {
                    float2 v = make_float2(acc[mi][ni][0], acc[mi][ni][1]);
                    *(float2*)&ob[(size_t)o * T_DIM + t] = v;
                }
                if (o + 8 < O_DIM) {
                    float2 v = make_float2(acc[mi][ni][2], acc[mi][ni][3]);
                    *(float2*)&ob[(size_t)(o + 8) * T_DIM + t] = v;
                }
            }
        }
    }
}

// ---------------- launch ----------------
extern "C" void kernel_launch(void* const* d_in, const int* in_sizes, int n_in,
                              void* d_out, int out_size) {
    const float* x = (const float*)d_in[0];       // [64, 270, 2000]
    const float* layout = (const float*)d_in[1];  // [270, 2]
    const float* heads = (const float*)d_in[2];   // [270, 2048]
    float* out = (float*)d_out;                   // [64, 270, 2000]

    cm_embed_kernel<<<C_DIM, 256>>>(layout);
    cm_scores_kernel<<<dim3(3, 3, 16), dim3(256)>>>(heads);
    cm_softmax_kernel<<<288, 288>>>(layout);
    cm_merge_kernel<<<dim3(48, 64), 128>>>(x, out);
}

// round 17
// speedup vs baseline: 1.0310x; 1.0310x over previous
#include <cuda_runtime.h>
#include <cstdint>

#define C_DIM 270
#define T_DIM 2000
#define O_DIM 270
#define D_DIM 2048

// ---------------- scratch (static device globals; no allocation) ----------------
__device__ float g_E[C_DIM * D_DIM];           // fourier embedding [C, D]
__device__ float g_Spart[16 * O_DIM * C_DIM];  // split-K score partials
__device__ uint4 g_Wf[18 * 34 * 32];           // softmaxed W in tf32 MMA A-fragment layout

__device__ __forceinline__ unsigned f2tf(float f) {
    unsigned r;
    asm("cvt.rna.tf32.f32 %0, %1;" : "=r"(r) : "f"(f));
    return r;
}
__device__ __forceinline__ uint32_t smem_u32(const void* p) {
    uint32_t a;
    asm("{ .reg .u64 t; cvta.to.shared.u64 t, %1; cvt.u32.u64 %0, t; }" : "=r"(a) : "l"(p));
    return a;
}
__device__ __forceinline__ void cp_async16(uint32_t dst, const void* src, int sz) {
    asm volatile("cp.async.cg.shared.global [%0], [%1], 16, %2;"
                 :: "r"(dst), "l"(src), "r"(sz));
}
#define CP_COMMIT() asm volatile("cp.async.commit_group;" ::: "memory")
#define CP_WAIT1() asm volatile("cp.async.wait_group 1;" ::: "memory")
#define CP_WAIT0() asm volatile("cp.async.wait_group 0;" ::: "memory")

// ---------------- kernel 1: fourier embedding via angle-sum factorization ----------------
__global__ void cm_embed_kernel(const float* __restrict__ layout) {
    int c = blockIdx.x;
    int tid = threadIdx.x;  // 256
    const float KK = 4.48798950512827605f;  // 2*pi / (1 + 2*0.2)
    __shared__ float cA[32], sA[32], cB[32], sB[32];

    if (tid < 32) {
        float px = layout[2 * c + 0] + 0.2f;
        sincosf(px * KK * (float)tid, &sA[tid], &cA[tid]);
    } else if (tid < 64) {
        int j = tid - 32;
        float py = layout[2 * c + 1] + 0.2f;
        sincosf(py * KK * (float)j, &sB[j], &cB[j]);
    }
    __syncthreads();

    for (int idx = tid; idx < 1024; idx += 256) {
        int i = idx >> 5, j = idx & 31;
        float ca = cA[i], sa = sA[i], cb = cB[j], sb = sB[j];
        g_E[c * D_DIM + idx] = ca * cb - sa * sb;          // cos(a+b)
        g_E[c * D_DIM + 1024 + idx] = sa * cb + ca * sb;   // sin(a+b)
    }
}

// ---------------- kernel 2: scores S[o,c] = sum_d H[o,d]*E[c,d], split-K=16 ----------------
__global__ void cm_scores_kernel(const float* __restrict__ heads) {
    __shared__ float As[64][21];
    __shared__ float Bs[64][21];
    int o0 = blockIdx.x * 64;
    int c0 = blockIdx.y * 64;
    int kz = blockIdx.z;
    int d_base = kz * 128;
    int tx = threadIdx.x, ty = threadIdx.y;
    int tid = ty * 16 + tx;
    float acc[4][4] = {};

    for (int dt = 0; dt < 128; dt += 16) {
        int row = tid >> 2;
        int col = (tid & 3) * 4;
        int d = d_base + dt + col;
        {
            int go = o0 + row;
            float4 v = (go < O_DIM) ? *(const float4*)&heads[(size_t)go * D_DIM + d]
                                    : make_float4(0.f, 0.f, 0.f, 0.f);
            As[row][col] = v.x; As[row][col + 1] = v.y;
            As[row][col + 2] = v.z; As[row][col + 3] = v.w;
        }
        {
            int gc = c0 + row;
            float4 v = (gc < C_DIM) ? *(const float4*)&g_E[(size_t)gc * D_DIM + d]
                                    : make_float4(0.f, 0.f, 0.f, 0.f);
            Bs[row][col] = v.x; Bs[row][col + 1] = v.y;
            Bs[row][col + 2] = v.z; Bs[row][col + 3] = v.w;
        }
        __syncthreads();
#pragma unroll
        for (int k = 0; k < 16; ++k) {
            float a[4], b[4];
#pragma unroll
            for (int i = 0; i < 4; ++i) a[i] = As[ty * 4 + i][k];
#pragma unroll
            for (int j = 0; j < 4; ++j) b[j] = Bs[tx * 4 + j][k];
#pragma unroll
            for (int i = 0; i < 4; ++i)
#pragma unroll
                for (int j = 0; j < 4; ++j) acc[i][j] += a[i] * b[j];
        }
        __syncthreads();
    }
#pragma unroll
    for (int i = 0; i < 4; ++i) {
        int o = o0 + ty * 4 + i;
        if (o >= O_DIM) continue;
#pragma unroll
        for (int j = 0; j < 4; ++j) {
            int c = c0 + tx * 4 + j;
            if (c < C_DIM) g_Spart[kz * (O_DIM * C_DIM) + o * C_DIM + c] = acc[i][j];
        }
    }
}

// ---------------- kernel 3: softmax over c, scattered straight into fragment layout ----------------
__global__ void cm_softmax_kernel(const float* __restrict__ layout) {
    int o = blockIdx.x;         // 0..287
    int tid = threadIdx.x;      // 288 threads
    int c = tid;
    int mblk = o >> 4, rr = o & 15;
    uint32_t* wf = (uint32_t*)g_Wf;

    auto scatter = [&](float v) {
        if (c >= 272) return;
        int kblk = c >> 3, q = c & 7;
        int lane, comp;
        if (q < 4) { lane = ((rr & 7) << 2) | q;       comp = (rr < 8) ? 0 : 1; }
        else       { lane = ((rr & 7) << 2) | (q - 4); comp = (rr < 8) ? 2 : 3; }
        wf[(((mblk * 34 + kblk) * 32 + lane) << 2) | comp] = f2tf(v);
    };

    if (o >= O_DIM) { scatter(0.f); return; }

    const float NEGINF = -__int_as_float(0x7f800000);
    float val = NEGINF;
    if (c < C_DIM) {
        float s = 0.f;
#pragma unroll
        for (int kz = 0; kz < 16; ++kz) s += g_Spart[kz * (O_DIM * C_DIM) + o * C_DIM + c];
        bool invalid = (layout[2 * c] == -0.1f) && (layout[2 * c + 1] == -0.1f);
        val = invalid ? NEGINF : s;
    }
    __shared__ float redm[9], reds[9];
    float m = val;
#pragma unroll
    for (int off = 16; off; off >>= 1) m = fmaxf(m, __shfl_xor_sync(0xffffffffu, m, off));
    if ((tid & 31) == 0) redm[tid >> 5] = m;
    __syncthreads();
    float mall = redm[0];
#pragma unroll
    for (int w = 1; w < 9; ++w) mall = fmaxf(mall, redm[w]);

    float e = (c < C_DIM) ? expf(val - mall) : 0.f;
    float s = e;
#pragma unroll
    for (int off = 16; off; off >>= 1) s += __shfl_xor_sync(0xffffffffu, s, off);
    if ((tid & 31) == 0) reds[tid >> 5] = s;
    __syncthreads();
    float tot = 0.f;
#pragma unroll
    for (int w = 0; w < 9; ++w) tot += reds[w];

    scatter(e / tot);   // c>=270 lanes have e==0 -> zero pad
}

// ---------------- kernel 4: out[b] = W @ x[b]  (tf32 mma.sync, 2-stage cp.async — R7 config) ----------------
#define BM 96
#define BN 128
#define BPADF 136   // 136 % 32 == 8 -> conflict-free tig groups; 16B aligned
#define KITERS 17   // 17 * k16 = 272

__global__ __launch_bounds__(128, 3) void cm_merge_kernel(const float* __restrict__ x,
                                                          float* __restrict__ out) {
    __shared__ float Bs[2][16 * BPADF];

    int mt = blockIdx.x % 3;   // m-tile fastest -> 3 CTAs share the x tile in L2
    int nt = blockIdx.x / 3;
    int b = blockIdx.y;
    int m0 = mt * BM;
    int t0 = nt * BN;
    const float* xb = x + (size_t)b * (C_DIM * T_DIM);
    float* ob = out + (size_t)b * (O_DIM * T_DIM);

    int tid = threadIdx.x;
    int lane = tid & 31, warp = tid >> 5;
    int wm = (warp & 1) * 48;          // 2 m-warps
    int wn = (warp >> 1) * 64;         // 2 n-warps of 64
    int gid = lane >> 2, tig = lane & 3;
    int mblkBase = mt * 6 + (warp & 1) * 3;

    uint32_t bs_base = smem_u32(&Bs[0][0]);

    float acc[3][8][4] = {};
    uint4 afA[3], afB[3];
    const uint4* wf = g_Wf;

    auto stage = [&](int it) {
        int buf = it & 1;
        int kg0 = it * 16;
        uint32_t base = bs_base + (uint32_t)buf * (16 * BPADF * 4);
#pragma unroll
        for (int i = 0; i < 4; ++i) {
            int idx = tid + i * 128;
            int row = idx >> 5, seg = idx & 31;
            int kg = kg0 + row;
            int t = t0 + seg * 4;
            int ok = (kg < C_DIM && t + 4 <= T_DIM);
            const float* src = &xb[(size_t)(ok ? kg : 0) * T_DIM + (ok ? t : 0)];
            cp_async16(base + (uint32_t)(row * BPADF + seg * 4) * 4, src, ok ? 16 : 0);
        }
        CP_COMMIT();
    };
    auto loadA = [&](uint4* af, int kblk) {
        kblk = kblk < 33 ? kblk : 33;
#pragma unroll
        for (int mi = 0; mi < 3; ++mi)
            af[mi] = wf[((mblkBase + mi) * 34 + kblk) * 32 + lane];
    };
    auto compute = [&](int buf, int kk, const uint4* af) {
        unsigned bf[8][2];
#pragma unroll
        for (int ni = 0; ni < 8; ++ni) {
            int cN = wn + ni * 8 + gid;
            bf[ni][0] = __float_as_uint(Bs[buf][(kk + tig) * BPADF + cN]);
            bf[ni][1] = __float_as_uint(Bs[buf][(kk + tig + 4) * BPADF + cN]);
        }
#pragma unroll
        for (int mi = 0; mi < 3; ++mi)
#pragma unroll
            for (int ni = 0; ni < 8; ++ni) {
                asm volatile(
                    "mma.sync.aligned.m16n8k8.row.col.f32.tf32.tf32.f32 "
                    "{%0,%1,%2,%3},{%4,%5,%6,%7},{%8,%9},{%0,%1,%2,%3};"
                    : "+f"(acc[mi][ni][0]), "+f"(acc[mi][ni][1]),
                      "+f"(acc[mi][ni][2]), "+f"(acc[mi][ni][3])
                    : "r"(af[mi].x), "r"(af[mi].y), "r"(af[mi].z), "r"(af[mi].w),
                      "r"(bf[ni][0]), "r"(bf[ni][1]));
            }
    };

    stage(0);
    stage(1);
    loadA(afA, 0);
#pragma unroll 1
    for (int it = 0; it < KITERS; ++it) {
        if (it + 1 < KITERS) { CP_WAIT1(); } else { CP_WAIT0(); }
        __syncthreads();
        loadA(afB, 2 * it + 1);
        compute(it & 1, 0, afA);
        loadA(afA, 2 * it + 2);
        compute(it & 1, 8, afB);
        __syncthreads();
        if (it + 2 < KITERS) stage(it + 2);
    }

    // epilogue
#pragma unroll
    for (int mi = 0; mi < 3; ++mi) {
        int o = m0 + wm + mi * 16 + gid;
#pragma unroll
        for (int ni = 0; ni < 8; ++ni) {
            int t = t0 + wn + ni * 8 + tig * 2;
            if (t < T_DIM) {
                if (o < O_DIM) {
                    float2 v = make_float2(acc[mi][ni][0], acc[mi][ni][1]);
                    *(float2*)&ob[(size_t)o * T_DIM + t] = v;
                }
                if (o + 8 < O_DIM) {
                    float2 v = make_float2(acc[mi][ni][2], acc[mi][ni][3]);
                    *(float2*)&ob[(size_t)(o + 8) * T_DIM + t] = v;
                }
            }
        }
    }
}

// ---------------- launch ----------------
extern "C" void kernel_launch(void* const* d_in, const int* in_sizes, int n_in,
                              void* d_out, int out_size) {
    const float* x = (const float*)d_in[0];       // [64, 270, 2000]
    const float* layout = (const float*)d_in[1];  // [270, 2]
    const float* heads = (const float*)d_in[2];   // [270, 2048]
    float* out = (float*)d_out;                   // [64, 270, 2000]

    cm_embed_kernel<<<C_DIM, 256>>>(layout);
    cm_scores_kernel<<<dim3(5, 5, 16), dim3(16, 16)>>>(heads);
    cm_softmax_kernel<<<288, 288>>>(layout);
    cm_merge_kernel<<<dim3(48, 64), 128>>>(x, out);
}